// round 1
// baseline (speedup 1.0000x reference)
#include <cuda_runtime.h>
#include <math.h>

// ---------------- problem constants (fixed shapes from setup_inputs) -------
#define NB      32          // batch
#define TSAMP   160000      // samples per batch
#define KFFT    1024        // n_fft
#define MWIN    800         // win_length
#define HOP     600
#define NBINS   256
#define NF      267         // 1 + (160000+1024-1024)/600
#define LMAXW   13
#define LMINW   3
#define FT      (NBINS*NF)  // 68352

// ---------------- scratch (__device__ globals, no allocation) --------------
__device__ float        g_win[MWIN];
__device__ float2       g_tw[KFFT/2];
__device__ float        g_Y[NB*NBINS*NF];
__device__ unsigned int g_keys[NB*FT];
__device__ int          g_nvalid[NB];

// ---------------- init: tables (double precision) + counter reset ----------
__global__ void init_kernel() {
    int i = threadIdx.x;
    if (i < MWIN) {
        double v = 0.5 - 0.5 * cos(2.0 * M_PI * (double)i / (double)MWIN);
        g_win[i] = (float)v;
    }
    if (i < KFFT/2) {
        double a = -2.0 * M_PI * (double)i / (double)KFFT;
        g_tw[i] = make_float2((float)cos(a), (float)sin(a));
    }
    if (i < NB) g_nvalid[i] = 0;
}

// ---------------- STFT power: one block per (batch, frame) -----------------
__global__ __launch_bounds__(256) void stft_kernel(const float* __restrict__ y) {
    const int f = blockIdx.x % NF;
    const int b = blockIdx.x / NF;
    __shared__ float  sre[KFFT];
    __shared__ float  sim[KFFT];
    __shared__ float2 stw[KFFT/2];
    const int tid = threadIdx.x;

    for (int i = tid; i < KFFT/2; i += 256) stw[i] = g_tw[i];

    const float* yb = y + (size_t)b * TSAMP;
    // load window-applied frame (reflect padding), bit-reversed into shared
    #pragma unroll
    for (int jj = 0; jj < 4; jj++) {
        int j = tid + jj * 256;
        float v = 0.0f;
        if (j >= 112 && j < 912) {              // zero-padded centered window
            int s = f * HOP + j - 512;          // center=True: pad K/2 = 512
            if (s < 0) s = -s;
            else if (s >= TSAMP) s = 2 * (TSAMP - 1) - s;
            v = __ldg(yb + s) * g_win[j - 112];
        }
        int r = __brev((unsigned)j) >> 22;      // 10-bit reversal
        sre[r] = v;
        sim[r] = 0.0f;
    }
    __syncthreads();

    // iterative radix-2 DIT FFT, 10 stages
    #pragma unroll
    for (int s = 1; s <= 10; s++) {
        const int half  = 1 << (s - 1);
        const int tsh   = 10 - s;
        #pragma unroll
        for (int it = 0; it < 2; it++) {
            int k   = tid + it * 256;           // 512 butterflies/stage
            int jjb = k & (half - 1);
            int grp = k >> (s - 1);
            int pos = (grp << s) + jjb;
            float2 w = stw[jjb << tsh];
            float xr = sre[pos + half], xi = sim[pos + half];
            float tr = w.x * xr - w.y * xi;
            float ti = w.x * xi + w.y * xr;
            float ar = sre[pos], ai = sim[pos];
            sre[pos]        = ar + tr;
            sim[pos]        = ai + ti;
            sre[pos + half] = ar - tr;
            sim[pos + half] = ai - ti;
        }
        __syncthreads();
    }

    // power spectrum, first 256 bins, layout [B, F, T]
    float re = sre[tid], im = sim[tid];
    g_Y[((size_t)b * NBINS + tid) * NF + f] = re * re + im * im;
}

// ---------------- RT60 per (batch, subband) ---------------------------------
__global__ __launch_bounds__(128) void rt60_kernel() {
    const int f = blockIdx.x % NBINS;
    const int b = blockIdx.x / NBINS;
    __shared__ float         sy[NF];
    __shared__ unsigned char sdl[NF];
    __shared__ int           sbest;
    __shared__ int           svalid;
    const int tid = threadIdx.x;
    if (tid == 0) { sbest = 0; svalid = 0; }

    const float* row = g_Y + ((size_t)b * NBINS + f) * NF;
    for (int t = tid; t < NF; t += 128) sy[t] = row[t];
    __syncthreads();

    // run length of strict decreases starting at t (capped at LMAX-1)
    int localbest = 0;
    for (int t = tid; t < NF; t += 128) {
        int c = 0;
        while (c < LMAXW - 1 && t + c + 1 < NF && sy[t + c + 1] < sy[t + c]) c++;
        sdl[t] = (unsigned char)c;
        int cand = c + 1;
        int rem  = NF - t;
        if (cand > rem)   cand = rem;
        if (cand > LMAXW) cand = LMAXW;
        if (cand > localbest) localbest = cand;
    }
    atomicMax(&sbest, localbest);
    __syncthreads();

    const int lenL = sbest;
    unsigned int* keys = g_keys + (size_t)b * FT + (size_t)f * NF;
    if (lenL < LMINW) {                          // no decreasing window at all
        for (int t = tid; t < NF; t += 128) keys[t] = 0xFFFFFFFFu;
        return;
    }

    const float xm  = 0.5f * (float)(lenL - 1);
    const float den = (float)lenL * (float)(lenL * lenL - 1) / 12.0f;
    int nv = 0;

    for (int t = tid; t < NF; t += 128) {
        unsigned int key = 0xFFFFFFFFu;
        if (t + lenL <= NF && (int)sdl[t] >= lenL - 1) {
            // EDC: reverse cumsum in same order as reference, then dB
            float acc = 0.0f;
            float db[LMAXW];
            for (int j = lenL - 1; j >= 0; j--) {
                acc += sy[t + j];
                db[j] = 10.0f * log10f(fmaxf(acc, 1e-10f));
            }
            float d0 = db[0];
            if (db[lenL - 1] - d0 < -10.0f) {    // selected
                float num = 0.0f;
                for (int j = 1; j < lenL; j++)
                    num += ((float)j - xm) * (db[j] - d0);
                float slope = num / den;         // slope <= 0 here
                float rt60  = (-60.0f / slope) * 0.0375f;  // HOP/FS
                unsigned int u = __float_as_uint(rt60);
                key = (u & 0x80000000u) ? ~u : (u | 0x80000000u);
                nv++;
            }
        }
        keys[t] = key;
    }

    atomicAdd(&svalid, nv);
    __syncthreads();
    if (tid == 0 && svalid) atomicAdd(&g_nvalid[b], svalid);
}

// ---------------- per-batch lower median via MSB radix select ---------------
__global__ __launch_bounds__(256) void median_kernel(const float* __restrict__ coeffs,
                                                     float* __restrict__ out) {
    const int b = blockIdx.x;
    __shared__ int          hist[256];
    __shared__ unsigned int sprefix;
    __shared__ int          sk;
    const int tid = threadIdx.x;

    const int nv = g_nvalid[b];
    if (nv == 0) {
        if (tid == 0) out[b] = 0.5f;            // DEFAULT_RT60 (>= 0.01)
        return;
    }
    if (tid == 0) { sprefix = 0u; sk = (nv - 1) >> 1; }

    const unsigned int* keys = g_keys + (size_t)b * FT;

    #pragma unroll
    for (int pass = 0; pass < 4; pass++) {
        hist[tid] = 0;
        __syncthreads();
        const int shift = 24 - 8 * pass;
        const unsigned int pfx   = sprefix;
        const unsigned int hmask = (pass == 0) ? 0u : (0xFFFFFFFFu << (shift + 8));
        for (int i = tid; i < FT; i += 256) {
            unsigned int key = keys[i];
            if ((key & hmask) == pfx)
                atomicAdd(&hist[(key >> shift) & 255], 1);
        }
        __syncthreads();
        if (tid == 0) {
            int k = sk, cum = 0, bin = 0;
            for (bin = 0; bin < 256; bin++) {
                if (cum + hist[bin] > k) break;
                cum += hist[bin];
            }
            sk = k - cum;
            sprefix = pfx | ((unsigned int)bin << shift);
        }
        __syncthreads();
    }

    if (tid == 0) {
        unsigned int key = sprefix;
        unsigned int u = (key & 0x80000000u) ? (key ^ 0x80000000u) : ~key;
        float med = __uint_as_float(u);
        float c0 = coeffs[0], c1 = coeffs[1];
        out[b] = fmaxf(c0 + c1 * med, 0.01f);
    }
}

// ---------------- launcher ---------------------------------------------------
extern "C" void kernel_launch(void* const* d_in, const int* in_sizes, int n_in,
                              void* d_out, int out_size) {
    const float* y      = (const float*)d_in[0];
    const float* coeffs = (const float*)d_in[1];
    float*       out    = (float*)d_out;

    init_kernel<<<1, 1024>>>();
    stft_kernel<<<NB * NF, 256>>>(y);
    rt60_kernel<<<NB * NBINS, 128>>>();
    median_kernel<<<NB, 256>>>(coeffs, out);
}

// round 2
// speedup vs baseline: 2.0338x; 2.0338x over previous
#include <cuda_runtime.h>
#include <math.h>

// ---------------- problem constants (fixed shapes from setup_inputs) -------
#define NB      32          // batch
#define TSAMP   160000      // samples per batch
#define KFFT    1024        // n_fft
#define MWIN    800         // win_length
#define HOP     600
#define NBINS   256
#define NF      267         // 1 + (160000+1024-1024)/600
#define NFP     134         // frame pairs (two real frames per complex FFT)
#define LMAXW   13
#define LMINW   3
#define FT      (NBINS*NF)  // 68352
#define HSEG    16          // histogram segments per batch
#define HCHUNK  4272        // ceil(FT/HSEG)

// ---------------- scratch (__device__ globals, no allocation) --------------
__device__ float        g_win[MWIN];
__device__ float2       g_tw[KFFT/2];
__device__ float        g_Y[NB*NBINS*NF];
__device__ unsigned int g_keys[NB*FT];
__device__ int          g_nvalid[NB];
__device__ int          g_hist[NB][256];
__device__ unsigned int g_pfx[NB];
__device__ int          g_k[NB];

// ---------------- init: tables (double precision) + state reset ------------
__global__ void init_kernel() {
    int i = threadIdx.x;
    if (i < MWIN) {
        double v = 0.5 - 0.5 * cos(2.0 * M_PI * (double)i / (double)MWIN);
        g_win[i] = (float)v;
    }
    if (i < KFFT/2) {
        double a = -2.0 * M_PI * (double)i / (double)KFFT;
        g_tw[i] = make_float2((float)cos(a), (float)sin(a));
    }
    if (i < NB) g_nvalid[i] = 0;
    for (int j = i; j < NB * 256; j += 1024) ((int*)g_hist)[j] = 0;
}

// ---------------- STFT power: one block per (batch, frame-pair) ------------
// Two real frames packed as re/im of one complex 1024-pt FFT; unpacked via
// Hermitian symmetry. Halves FFT count vs one-frame-per-block.
__global__ __launch_bounds__(256) void stft_kernel(const float* __restrict__ y) {
    const int p  = blockIdx.x % NFP;
    const int b  = blockIdx.x / NFP;
    const int fa = 2 * p;
    const int fb = 2 * p + 1;          // may be NF (zero frame)
    __shared__ float  sre[KFFT];
    __shared__ float  sim[KFFT];
    __shared__ float2 stw[KFFT/2];
    const int tid = threadIdx.x;

    for (int i = tid; i < KFFT/2; i += 256) stw[i] = g_tw[i];

    const float* yb = y + (size_t)b * TSAMP;
    #pragma unroll
    for (int jj = 0; jj < 4; jj++) {
        int j = tid + jj * 256;
        float va = 0.0f, vb = 0.0f;
        if (j >= 112 && j < 912) {               // zero-padded centered window
            float w = g_win[j - 112];
            int sa = fa * HOP + j - 512;         // center=True: pad K/2 = 512
            if (sa < 0) sa = -sa;
            else if (sa >= TSAMP) sa = 2 * (TSAMP - 1) - sa;
            va = __ldg(yb + sa) * w;
            if (fb < NF) {
                int sb = fb * HOP + j - 512;
                if (sb < 0) sb = -sb;
                else if (sb >= TSAMP) sb = 2 * (TSAMP - 1) - sb;
                vb = __ldg(yb + sb) * w;
            }
        }
        int r = __brev((unsigned)j) >> 22;       // 10-bit reversal
        sre[r] = va;
        sim[r] = vb;
    }
    __syncthreads();

    // iterative radix-2 DIT FFT, 10 stages
    #pragma unroll
    for (int s = 1; s <= 10; s++) {
        const int half = 1 << (s - 1);
        const int tsh  = 10 - s;
        #pragma unroll
        for (int it = 0; it < 2; it++) {
            int k   = tid + it * 256;            // 512 butterflies/stage
            int jjb = k & (half - 1);
            int grp = k >> (s - 1);
            int pos = (grp << s) + jjb;
            float2 w = stw[jjb << tsh];
            float xr = sre[pos + half], xi = sim[pos + half];
            float tr = w.x * xr - w.y * xi;
            float ti = w.x * xi + w.y * xr;
            float ar = sre[pos], ai = sim[pos];
            sre[pos]        = ar + tr;
            sim[pos]        = ai + ti;
            sre[pos + half] = ar - tr;
            sim[pos + half] = ai - ti;
        }
        __syncthreads();
    }

    // unpack two real spectra from one complex FFT; power, layout [B, F, T]
    const int k  = tid;
    const int km = (KFFT - k) & (KFFT - 1);
    float ar = sre[k],  ai = sim[k];
    float br = sre[km], bi = -sim[km];           // conj(Z[K-k])
    float xar = 0.5f * (ar + br), xai = 0.5f * (ai + bi);
    float dr  = ar - br,          di  = ai - bi;
    float xbr = 0.5f * di,        xbi = -0.5f * dr;
    float* Yrow = g_Y + ((size_t)b * NBINS + k) * NF;
    Yrow[fa] = xar * xar + xai * xai;
    if (fb < NF) Yrow[fb] = xbr * xbr + xbi * xbi;
}

// ---------------- RT60 per (batch, subband) ---------------------------------
__global__ __launch_bounds__(128) void rt60_kernel() {
    const int f = blockIdx.x % NBINS;
    const int b = blockIdx.x / NBINS;
    __shared__ float         sy[NF];
    __shared__ unsigned char sdl[NF];
    __shared__ int           sbest;
    __shared__ int           svalid;
    const int tid = threadIdx.x;
    if (tid == 0) { sbest = 0; svalid = 0; }

    const float* row = g_Y + ((size_t)b * NBINS + f) * NF;
    for (int t = tid; t < NF; t += 128) sy[t] = row[t];
    __syncthreads();

    // run length of strict decreases starting at t (capped at LMAX-1)
    int localbest = 0;
    for (int t = tid; t < NF; t += 128) {
        int c = 0;
        while (c < LMAXW - 1 && t + c + 1 < NF && sy[t + c + 1] < sy[t + c]) c++;
        sdl[t] = (unsigned char)c;
        int cand = c + 1;
        int rem  = NF - t;
        if (cand > rem)   cand = rem;
        if (cand > LMAXW) cand = LMAXW;
        if (cand > localbest) localbest = cand;
    }
    atomicMax(&sbest, localbest);
    __syncthreads();

    const int lenL = sbest;
    unsigned int* keys = g_keys + (size_t)b * FT + (size_t)f * NF;
    if (lenL < LMINW) {                          // no decreasing window at all
        for (int t = tid; t < NF; t += 128) keys[t] = 0xFFFFFFFFu;
        return;
    }

    const float xm  = 0.5f * (float)(lenL - 1);
    const float den = (float)lenL * (float)(lenL * lenL - 1) / 12.0f;
    int nv = 0;

    for (int t = tid; t < NF; t += 128) {
        unsigned int key = 0xFFFFFFFFu;
        if (t + lenL <= NF && (int)sdl[t] >= lenL - 1) {
            // EDC: reverse cumsum in same order as reference, then dB
            float acc = 0.0f;
            float db[LMAXW];
            for (int j = lenL - 1; j >= 0; j--) {
                acc += sy[t + j];
                db[j] = 10.0f * log10f(fmaxf(acc, 1e-10f));
            }
            float d0 = db[0];
            if (db[lenL - 1] - d0 < -10.0f) {    // selected
                float num = 0.0f;
                for (int j = 1; j < lenL; j++)
                    num += ((float)j - xm) * (db[j] - d0);
                float slope = num / den;         // slope <= 0 here
                float rt60  = (-60.0f / slope) * 0.0375f;  // HOP/FS
                unsigned int u = __float_as_uint(rt60);
                key = (u & 0x80000000u) ? ~u : (u | 0x80000000u);
                nv++;
            }
        }
        keys[t] = key;
    }

    atomicAdd(&svalid, nv);
    __syncthreads();
    if (tid == 0 && svalid) atomicAdd(&g_nvalid[b], svalid);
}

// ---------------- median: multi-block 8-bit radix select --------------------
// hist pass: 32 batches x 16 segments = 512 blocks, shared hist -> global
__global__ __launch_bounds__(256) void hist_kernel(int pass) {
    const int b   = blockIdx.x >> 4;
    const int seg = blockIdx.x & 15;
    __shared__ int h[256];
    const int tid = threadIdx.x;
    h[tid] = 0;
    __syncthreads();

    const int shift = 24 - 8 * pass;
    const unsigned int pfx   = (pass == 0) ? 0u : g_pfx[b];
    const unsigned int hmask = (pass == 0) ? 0u : (0xFFFFFFFFu << (shift + 8));
    const unsigned int* keys = g_keys + (size_t)b * FT;
    const int start = seg * HCHUNK;
    const int end   = (start + HCHUNK < FT) ? start + HCHUNK : FT;
    for (int i = start + tid; i < end; i += 256) {
        unsigned int key = keys[i];
        if ((key & hmask) == pfx) atomicAdd(&h[(key >> shift) & 255], 1);
    }
    __syncthreads();
    if (h[tid]) atomicAdd(&g_hist[b][tid], h[tid]);
}

// select pass: 32 blocks; picks bin containing k-th element, resets hist
__global__ __launch_bounds__(256) void select_kernel(int pass,
                                                     const float* __restrict__ coeffs,
                                                     float* __restrict__ out) {
    const int b   = blockIdx.x;
    const int tid = threadIdx.x;
    __shared__ int h[256];
    h[tid] = g_hist[b][tid];
    g_hist[b][tid] = 0;                           // reset for next pass
    __syncthreads();

    if (tid == 0) {
        int k = (pass == 0) ? ((g_nvalid[b] - 1) >> 1) : g_k[b];
        if (k < 0) k = 0;
        int cum = 0, bin = 0;
        for (bin = 0; bin < 256; bin++) {
            if (cum + h[bin] > k) break;
            cum += h[bin];
        }
        if (bin > 255) bin = 255;
        g_k[b] = k - cum;
        const int shift = 24 - 8 * pass;
        unsigned int pfx = ((pass == 0) ? 0u : g_pfx[b]) | ((unsigned int)bin << shift);
        g_pfx[b] = pfx;
        if (pass == 3) {
            if (g_nvalid[b] == 0) {
                out[b] = 0.5f;                    // DEFAULT_RT60 (>= 0.01)
            } else {
                unsigned int u = (pfx & 0x80000000u) ? (pfx ^ 0x80000000u) : ~pfx;
                float med = __uint_as_float(u);
                out[b] = fmaxf(coeffs[0] + coeffs[1] * med, 0.01f);
            }
        }
    }
}

// ---------------- launcher ---------------------------------------------------
extern "C" void kernel_launch(void* const* d_in, const int* in_sizes, int n_in,
                              void* d_out, int out_size) {
    const float* y      = (const float*)d_in[0];
    const float* coeffs = (const float*)d_in[1];
    float*       out    = (float*)d_out;

    init_kernel<<<1, 1024>>>();
    stft_kernel<<<NB * NFP, 256>>>(y);
    rt60_kernel<<<NB * NBINS, 128>>>();
    #pragma unroll
    for (int pass = 0; pass < 4; pass++) {
        hist_kernel<<<NB * HSEG, 256>>>(pass);
        select_kernel<<<NB, 256>>>(pass, coeffs, out);
    }
}

// round 3
// speedup vs baseline: 2.4622x; 1.2106x over previous
#include <cuda_runtime.h>
#include <math.h>

// ---------------- problem constants (fixed shapes from setup_inputs) -------
#define NB      32          // batch
#define TSAMP   160000      // samples per batch
#define KFFT    1024        // n_fft
#define MWIN    800         // win_length
#define HOP     600
#define NBINS   256
#define NF      267         // 1 + (160000+1024-1024)/600
#define NFP     134         // frame pairs (two real frames per complex FFT)
#define LMAXW   13
#define LMINW   3
#define FT      (NBINS*NF)  // 68352
#define TWN     768         // twiddle table: exp(-2pi i k/1024), k<768
#define HSEG    64          // histogram segments per batch
#define HCHUNK  1068        // FT / HSEG exactly

// ---------------- scratch (__device__ globals, no allocation) --------------
__device__ float        g_win[MWIN];
__device__ float2       g_tw[TWN];
__device__ float        g_Y[NB*NBINS*NF];
__device__ unsigned int g_keys[NB*FT];
__device__ int          g_nvalid[NB];
__device__ int          g_hist[NB][256];
__device__ unsigned int g_pfx[NB];
__device__ int          g_k[NB];
__device__ int          g_done[4];

// ---------------- init: tables (double precision) + state reset ------------
__global__ __launch_bounds__(256) void init_kernel() {
    int gid = blockIdx.x * 256 + threadIdx.x;     // grid 8x256 -> 2048
    if (gid < MWIN) {
        double v = 0.5 - 0.5 * cos(2.0 * M_PI * (double)gid / (double)MWIN);
        g_win[gid] = (float)v;
    }
    int tj = gid - MWIN;
    if (tj >= 0 && tj < TWN) {
        double a = -2.0 * M_PI * (double)tj / (double)KFFT;
        g_tw[tj] = make_float2((float)cos(a), (float)sin(a));
    }
    if (gid < NB) g_nvalid[gid] = 0;
    if (gid < 4)  g_done[gid] = 0;
    for (int j = gid; j < NB * 256; j += 2048) ((int*)g_hist)[j] = 0;
}

// ---------------- STFT power: one block per (batch, frame-pair) ------------
// Two real frames packed as re/im of one complex 1024-pt FFT (radix-4
// Stockham autosort, 5 iterations), unpacked via Hermitian symmetry.
__global__ __launch_bounds__(256) void stft_kernel(const float* __restrict__ y) {
    const int p  = blockIdx.x % NFP;
    const int b  = blockIdx.x / NFP;
    const int fa = 2 * p;
    const int fb = 2 * p + 1;                    // may be NF (dropped)
    __shared__ float  Are[KFFT], Aim[KFFT], Bre[KFFT], Bim[KFFT];
    __shared__ float2 stw[TWN];
    const int tid = threadIdx.x;

    for (int i = tid; i < TWN; i += 256) stw[i] = g_tw[i];

    const float* yb = y + (size_t)b * TSAMP;
    #pragma unroll
    for (int jj = 0; jj < 4; jj++) {
        int j = tid + jj * 256;
        float va = 0.0f, vb = 0.0f;
        if (j >= 112 && j < 912) {               // zero-padded centered window
            float w = g_win[j - 112];
            int sa = fa * HOP + j - 512;         // center=True: pad K/2 = 512
            if (sa < 0) sa = -sa;
            else if (sa >= TSAMP) sa = 2 * (TSAMP - 1) - sa;
            va = __ldg(yb + sa) * w;
            if (fb < NF) {
                int sb = fb * HOP + j - 512;
                if (sb < 0) sb = -sb;
                else if (sb >= TSAMP) sb = 2 * (TSAMP - 1) - sb;
                vb = __ldg(yb + sb) * w;
            }
        }
        Are[j] = va;                             // natural order (autosort)
        Aim[j] = vb;
    }
    __syncthreads();

    // 5 radix-4 Stockham iterations, Ns = 1,4,16,64,256
    float *sr = Are, *si = Aim, *dr = Bre, *di = Bim;
    #pragma unroll
    for (int it = 0; it < 5; it++) {
        const int Ns = 1 << (2 * it);
        const int m  = tid & (Ns - 1);
        const int ts = 256 >> (2 * it);          // twiddle step = 256/Ns
        float v0r = sr[tid],       v0i = si[tid];
        float v1r = sr[tid + 256], v1i = si[tid + 256];
        float v2r = sr[tid + 512], v2i = si[tid + 512];
        float v3r = sr[tid + 768], v3i = si[tid + 768];
        const int tb = m * ts;
        float2 w1 = stw[tb], w2 = stw[2 * tb], w3 = stw[3 * tb];
        float a1r = w1.x * v1r - w1.y * v1i, a1i = w1.x * v1i + w1.y * v1r;
        float a2r = w2.x * v2r - w2.y * v2i, a2i = w2.x * v2i + w2.y * v2r;
        float a3r = w3.x * v3r - w3.y * v3i, a3i = w3.x * v3i + w3.y * v3r;
        float t0r = v0r + a2r, t0i = v0i + a2i;
        float t1r = v0r - a2r, t1i = v0i - a2i;
        float t2r = a1r + a3r, t2i = a1i + a3i;
        float t3r = a1r - a3r, t3i = a1i - a3i;
        const int idxD = ((tid >> (2 * it)) << (2 * it + 2)) + m;
        dr[idxD]          = t0r + t2r; di[idxD]          = t0i + t2i;
        dr[idxD + Ns]     = t1r + t3i; di[idxD + Ns]     = t1i - t3r;  // -i*(v1-v3)
        dr[idxD + 2 * Ns] = t0r - t2r; di[idxD + 2 * Ns] = t0i - t2i;
        dr[idxD + 3 * Ns] = t1r - t3i; di[idxD + 3 * Ns] = t1i + t3r;
        __syncthreads();
        float* tp;
        tp = sr; sr = dr; dr = tp;
        tp = si; si = di; di = tp;
    }

    // unpack two real spectra from one complex FFT; power, layout [B, F, T]
    const int k  = tid;
    const int km = (KFFT - k) & (KFFT - 1);
    float ar = sr[k],  ai = si[k];
    float br = sr[km], bi = -si[km];             // conj(Z[K-k])
    float xar = 0.5f * (ar + br), xai = 0.5f * (ai + bi);
    float ddr = ar - br,          ddi = ai - bi;
    float xbr = 0.5f * ddi,       xbi = -0.5f * ddr;
    float* Yrow = g_Y + ((size_t)b * NBINS + k) * NF;
    Yrow[fa] = xar * xar + xai * xai;
    if (fb < NF) Yrow[fb] = xbr * xbr + xbi * xbi;
}

// ---------------- RT60 per (batch, subband) ---------------------------------
__global__ __launch_bounds__(128) void rt60_kernel() {
    const int f = blockIdx.x % NBINS;
    const int b = blockIdx.x / NBINS;
    __shared__ float         sy[NF];
    __shared__ unsigned char sdl[NF];
    __shared__ int           sbest;
    __shared__ int           svalid;
    const int tid = threadIdx.x;
    if (tid == 0) { sbest = 0; svalid = 0; }

    const float* row = g_Y + ((size_t)b * NBINS + f) * NF;
    for (int t = tid; t < NF; t += 128) sy[t] = row[t];
    __syncthreads();

    // run length of strict decreases starting at t (capped at LMAX-1)
    int localbest = 0;
    for (int t = tid; t < NF; t += 128) {
        int c = 0;
        while (c < LMAXW - 1 && t + c + 1 < NF && sy[t + c + 1] < sy[t + c]) c++;
        sdl[t] = (unsigned char)c;
        int cand = c + 1;
        int rem  = NF - t;
        if (cand > rem)   cand = rem;
        if (cand > LMAXW) cand = LMAXW;
        if (cand > localbest) localbest = cand;
    }
    atomicMax(&sbest, localbest);
    __syncthreads();

    const int lenL = sbest;
    unsigned int* keys = g_keys + (size_t)b * FT + (size_t)f * NF;
    if (lenL < LMINW) {                          // no decreasing window at all
        for (int t = tid; t < NF; t += 128) keys[t] = 0xFFFFFFFFu;
        return;
    }

    const float xm  = 0.5f * (float)(lenL - 1);
    const float den = (float)lenL * (float)(lenL * lenL - 1) / 12.0f;
    int nv = 0;

    for (int t = tid; t < NF; t += 128) {
        unsigned int key = 0xFFFFFFFFu;
        if (t + lenL <= NF && (int)sdl[t] >= lenL - 1) {
            // EDC: reverse cumsum in same order as reference, then dB
            float acc = 0.0f;
            float db[LMAXW];
            for (int j = lenL - 1; j >= 0; j--) {
                acc += sy[t + j];
                db[j] = 10.0f * log10f(fmaxf(acc, 1e-10f));
            }
            float d0 = db[0];
            if (db[lenL - 1] - d0 < -10.0f) {    // selected
                float num = 0.0f;
                for (int j = 1; j < lenL; j++)
                    num += ((float)j - xm) * (db[j] - d0);
                float slope = num / den;         // slope <= 0 here
                float rt60  = (-60.0f / slope) * 0.0375f;  // HOP/FS
                unsigned int u = __float_as_uint(rt60);
                key = (u & 0x80000000u) ? ~u : (u | 0x80000000u);
                nv++;
            }
        }
        keys[t] = key;
    }

    atomicAdd(&svalid, nv);
    __syncthreads();
    if (tid == 0 && svalid) atomicAdd(&g_nvalid[b], svalid);
}

// ---------------- median: fused histogram + last-block select ---------------
// One kernel per radix pass. 2048 blocks build per-batch histograms; the
// last-finishing block performs all 32 selects (warp-scan over 256 bins)
// and resets the histogram for the next pass / next replay.
__global__ __launch_bounds__(256) void pass_kernel(int pass,
                                                   const float* __restrict__ coeffs,
                                                   float* __restrict__ out) {
    const int b   = blockIdx.x >> 6;
    const int seg = blockIdx.x & 63;
    const int tid = threadIdx.x;
    __shared__ int  h[256];
    __shared__ int  slast;
    __shared__ int  sh[NB * 256];

    h[tid] = 0;
    __syncthreads();

    const int shift = 24 - 8 * pass;
    const unsigned int pfx   = (pass == 0) ? 0u : g_pfx[b];
    const unsigned int hmask = (pass == 0) ? 0u : (0xFFFFFFFFu << (shift + 8));
    const unsigned int* keys = g_keys + (size_t)b * FT + seg * HCHUNK;
    #pragma unroll
    for (int q = 0; q < HCHUNK / 256; q++) {     // 1068 = 4*256 + 44
        unsigned int key = keys[tid + q * 256];
        if ((key & hmask) == pfx) atomicAdd(&h[(key >> shift) & 255], 1);
    }
    if (tid < HCHUNK - (HCHUNK / 256) * 256) {
        unsigned int key = keys[tid + (HCHUNK / 256) * 256];
        if ((key & hmask) == pfx) atomicAdd(&h[(key >> shift) & 255], 1);
    }
    __syncthreads();
    if (h[tid]) atomicAdd(&g_hist[b][tid], h[tid]);
    __syncthreads();

    if (tid == 0) {
        __threadfence();
        int t = atomicAdd(&g_done[pass], 1);
        slast = (t == (int)gridDim.x - 1);
    }
    __syncthreads();
    if (!slast) return;
    __threadfence();

    // ---- select: one warp handles 4 batches via scan over 256 bins ----
    for (int i = tid; i < NB * 256; i += 256) sh[i] = ((int*)g_hist)[i];
    __syncthreads();

    const int w = tid >> 5, lane = tid & 31;
    for (int b2 = w; b2 < NB; b2 += 8) {
        const int base = lane * 8;
        int c[8]; int s = 0;
        #pragma unroll
        for (int q = 0; q < 8; q++) { c[q] = sh[b2 * 256 + base + q]; s += c[q]; }
        int excl = s;
        #pragma unroll
        for (int off = 1; off < 32; off <<= 1) {
            int n = __shfl_up_sync(0xFFFFFFFFu, excl, off);
            if (lane >= off) excl += n;
        }
        excl -= s;                                // exclusive prefix across lanes
        int k0 = (pass == 0) ? ((g_nvalid[b2] - 1) >> 1) : g_k[b2];
        if (k0 < 0) k0 = 0;
        int bin = 256, cumAt = 0, cum = excl;
        #pragma unroll
        for (int q = 0; q < 8; q++) {
            if (bin == 256 && cum + c[q] > k0) { bin = base + q; cumAt = cum; }
            cum += c[q];
        }
        unsigned int ball = __ballot_sync(0xFFFFFFFFu, bin < 256);
        int src = __ffs(ball) - 1;                // guaranteed: total >= k0+1
        if (lane == src) {
            g_k[b2] = k0 - cumAt;
            unsigned int npfx = ((pass == 0) ? 0u : g_pfx[b2])
                              | ((unsigned int)bin << shift);
            g_pfx[b2] = npfx;
            if (pass == 3) {
                if (g_nvalid[b2] == 0) {
                    out[b2] = 0.5f;               // DEFAULT_RT60 (>= 0.01)
                } else {
                    unsigned int u = (npfx & 0x80000000u) ? (npfx ^ 0x80000000u)
                                                          : ~npfx;
                    float med = __uint_as_float(u);
                    out[b2] = fmaxf(coeffs[0] + coeffs[1] * med, 0.01f);
                }
            }
        }
    }
    __syncthreads();
    // reset histogram for next pass / next replay
    for (int i = tid; i < NB * 256; i += 256) ((int*)g_hist)[i] = 0;
}

// ---------------- launcher ---------------------------------------------------
extern "C" void kernel_launch(void* const* d_in, const int* in_sizes, int n_in,
                              void* d_out, int out_size) {
    const float* y      = (const float*)d_in[0];
    const float* coeffs = (const float*)d_in[1];
    float*       out    = (float*)d_out;

    init_kernel<<<8, 256>>>();
    stft_kernel<<<NB * NFP, 256>>>(y);
    rt60_kernel<<<NB * NBINS, 128>>>();
    for (int pass = 0; pass < 4; pass++)
        pass_kernel<<<NB * HSEG, 256>>>(pass, coeffs, out);
}

// round 4
// speedup vs baseline: 3.8935x; 1.5813x over previous
#include <cuda_runtime.h>
#include <math.h>

// ---------------- problem constants (fixed shapes from setup_inputs) -------
#define NB      32          // batch
#define TSAMP   160000      // samples per batch
#define KFFT    1024        // n_fft
#define MWIN    800         // win_length
#define HOP     600
#define NBINS   256
#define NF      267         // 1 + (160000+1024-1024)/600
#define NFP     134         // frame pairs (two real frames per complex FFT)
#define LMAXW   13
#define LMINW   3
#define FT      (NBINS*NF)  // 68352 (worst-case valid keys per batch)
#define TWN     768         // twiddle table: exp(-2pi i k/1024), k<768
#define SMEMK   8192        // median smem key cache capacity

// ---------------- scratch (__device__ globals, no allocation) --------------
__device__ float        g_win[MWIN];
__device__ float2       g_tw[TWN];
__device__ float        g_Y[NB*NBINS*NF];
__device__ unsigned int g_keys[NB*FT];          // compacted valid keys
__device__ int          g_nvalid[NB];

// ---------------- init: tables (double precision) + state reset ------------
__global__ __launch_bounds__(256) void init_kernel() {
    int gid = blockIdx.x * 256 + threadIdx.x;     // grid 8x256 -> 2048
    if (gid < MWIN) {
        double v = 0.5 - 0.5 * cos(2.0 * M_PI * (double)gid / (double)MWIN);
        g_win[gid] = (float)v;
    }
    int tj = gid - MWIN;
    if (tj >= 0 && tj < TWN) {
        double a = -2.0 * M_PI * (double)tj / (double)KFFT;
        g_tw[tj] = make_float2((float)cos(a), (float)sin(a));
    }
    if (gid < NB) g_nvalid[gid] = 0;
}

// ---------------- STFT power: one block per (batch, frame-pair) ------------
// Two real frames packed as re/im of one complex 1024-pt FFT (radix-4
// Stockham autosort, 5 iterations), unpacked via Hermitian symmetry.
__global__ __launch_bounds__(256) void stft_kernel(const float* __restrict__ y) {
    const int p  = blockIdx.x % NFP;
    const int b  = blockIdx.x / NFP;
    const int fa = 2 * p;
    const int fb = 2 * p + 1;                    // may be NF (dropped)
    __shared__ float  Are[KFFT], Aim[KFFT], Bre[KFFT], Bim[KFFT];
    __shared__ float2 stw[TWN];
    const int tid = threadIdx.x;

    for (int i = tid; i < TWN; i += 256) stw[i] = g_tw[i];

    const float* yb = y + (size_t)b * TSAMP;
    #pragma unroll
    for (int jj = 0; jj < 4; jj++) {
        int j = tid + jj * 256;
        float va = 0.0f, vb = 0.0f;
        if (j >= 112 && j < 912) {               // zero-padded centered window
            float w = g_win[j - 112];
            int sa = fa * HOP + j - 512;         // center=True: pad K/2 = 512
            if (sa < 0) sa = -sa;
            else if (sa >= TSAMP) sa = 2 * (TSAMP - 1) - sa;
            va = __ldg(yb + sa) * w;
            if (fb < NF) {
                int sb = fb * HOP + j - 512;
                if (sb < 0) sb = -sb;
                else if (sb >= TSAMP) sb = 2 * (TSAMP - 1) - sb;
                vb = __ldg(yb + sb) * w;
            }
        }
        Are[j] = va;                             // natural order (autosort)
        Aim[j] = vb;
    }
    __syncthreads();

    // 5 radix-4 Stockham iterations, Ns = 1,4,16,64,256
    float *sr = Are, *si = Aim, *dr = Bre, *di = Bim;
    #pragma unroll
    for (int it = 0; it < 5; it++) {
        const int Ns = 1 << (2 * it);
        const int m  = tid & (Ns - 1);
        const int ts = 256 >> (2 * it);          // twiddle step = 256/Ns
        float v0r = sr[tid],       v0i = si[tid];
        float v1r = sr[tid + 256], v1i = si[tid + 256];
        float v2r = sr[tid + 512], v2i = si[tid + 512];
        float v3r = sr[tid + 768], v3i = si[tid + 768];
        const int tb = m * ts;
        float2 w1 = stw[tb], w2 = stw[2 * tb], w3 = stw[3 * tb];
        float a1r = w1.x * v1r - w1.y * v1i, a1i = w1.x * v1i + w1.y * v1r;
        float a2r = w2.x * v2r - w2.y * v2i, a2i = w2.x * v2i + w2.y * v2r;
        float a3r = w3.x * v3r - w3.y * v3i, a3i = w3.x * v3i + w3.y * v3r;
        float t0r = v0r + a2r, t0i = v0i + a2i;
        float t1r = v0r - a2r, t1i = v0i - a2i;
        float t2r = a1r + a3r, t2i = a1i + a3i;
        float t3r = a1r - a3r, t3i = a1i - a3i;
        const int idxD = ((tid >> (2 * it)) << (2 * it + 2)) + m;
        dr[idxD]          = t0r + t2r; di[idxD]          = t0i + t2i;
        dr[idxD + Ns]     = t1r + t3i; di[idxD + Ns]     = t1i - t3r;  // -i*(v1-v3)
        dr[idxD + 2 * Ns] = t0r - t2r; di[idxD + 2 * Ns] = t0i - t2i;
        dr[idxD + 3 * Ns] = t1r - t3i; di[idxD + 3 * Ns] = t1i + t3r;
        __syncthreads();
        float* tp;
        tp = sr; sr = dr; dr = tp;
        tp = si; si = di; di = tp;
    }

    // unpack two real spectra from one complex FFT; power, layout [B, F, T]
    const int k  = tid;
    const int km = (KFFT - k) & (KFFT - 1);
    float ar = sr[k],  ai = si[k];
    float br = sr[km], bi = -si[km];             // conj(Z[K-k])
    float xar = 0.5f * (ar + br), xai = 0.5f * (ai + bi);
    float ddr = ar - br,          ddi = ai - bi;
    float xbr = 0.5f * ddi,       xbi = -0.5f * ddr;
    float* Yrow = g_Y + ((size_t)b * NBINS + k) * NF;
    Yrow[fa] = xar * xar + xai * xai;
    if (fb < NF) Yrow[fb] = xbr * xbr + xbi * xbi;
}

// ---------------- RT60 per (batch, subband): compact valid keys -------------
__global__ __launch_bounds__(128) void rt60_kernel() {
    const int f = blockIdx.x % NBINS;
    const int b = blockIdx.x / NBINS;
    __shared__ float         sy[NF];
    __shared__ unsigned char sdl[NF];
    __shared__ int           sbest;
    const int tid = threadIdx.x;
    if (tid == 0) sbest = 0;

    const float* row = g_Y + ((size_t)b * NBINS + f) * NF;
    for (int t = tid; t < NF; t += 128) sy[t] = row[t];
    __syncthreads();

    // run length of strict decreases starting at t (capped at LMAX-1)
    int localbest = 0;
    for (int t = tid; t < NF; t += 128) {
        int c = 0;
        while (c < LMAXW - 1 && t + c + 1 < NF && sy[t + c + 1] < sy[t + c]) c++;
        sdl[t] = (unsigned char)c;
        int cand = c + 1;
        int rem  = NF - t;
        if (cand > rem)   cand = rem;
        if (cand > LMAXW) cand = LMAXW;
        if (cand > localbest) localbest = cand;
    }
    atomicMax(&sbest, localbest);
    __syncthreads();

    const int lenL = sbest;
    if (lenL < LMINW) return;                    // no decreasing window at all

    const float xm  = 0.5f * (float)(lenL - 1);
    const float den = (float)lenL * (float)(lenL * lenL - 1) / 12.0f;

    for (int t = tid; t < NF; t += 128) {
        if (t + lenL <= NF && (int)sdl[t] >= lenL - 1) {
            // EDC: reverse cumsum in same order as reference, then dB
            float acc = 0.0f;
            float db[LMAXW];
            for (int j = lenL - 1; j >= 0; j--) {
                acc += sy[t + j];
                db[j] = 10.0f * log10f(fmaxf(acc, 1e-10f));
            }
            float d0 = db[0];
            if (db[lenL - 1] - d0 < -10.0f) {    // selected
                float num = 0.0f;
                for (int j = 1; j < lenL; j++)
                    num += ((float)j - xm) * (db[j] - d0);
                float slope = num / den;         // slope <= 0 here
                float rt60  = (-60.0f / slope) * 0.0375f;  // HOP/FS
                unsigned int u = __float_as_uint(rt60);
                unsigned int key = (u & 0x80000000u) ? ~u : (u | 0x80000000u);
                int pos = atomicAdd(&g_nvalid[b], 1);
                g_keys[(size_t)b * FT + pos] = key;
            }
        }
    }
}

// ---------------- median: one block per batch, 4-pass radix select ----------
__global__ __launch_bounds__(512) void median_kernel(const float* __restrict__ coeffs,
                                                     float* __restrict__ out) {
    const int b   = blockIdx.x;
    const int tid = threadIdx.x;
    __shared__ unsigned int skeys[SMEMK];
    __shared__ int          hist[256];
    __shared__ unsigned int s_pfx;
    __shared__ int          s_k;

    const int n = g_nvalid[b];
    if (n == 0) {
        if (tid == 0) out[b] = 0.5f;             // DEFAULT_RT60 (>= 0.01)
        return;
    }
    const unsigned int* gk = g_keys + (size_t)b * FT;
    const bool fits = (n <= SMEMK);
    if (fits)
        for (int i = tid; i < n; i += 512) skeys[i] = gk[i];
    if (tid == 0) { s_pfx = 0u; s_k = (n - 1) >> 1; }
    __syncthreads();

    #pragma unroll
    for (int pass = 0; pass < 4; pass++) {
        for (int i = tid; i < 256; i += 512) hist[i] = 0;
        __syncthreads();
        const int shift = 24 - 8 * pass;
        const unsigned int pfx   = s_pfx;
        const unsigned int hmask = (pass == 0) ? 0u : (0xFFFFFFFFu << (shift + 8));
        if (fits) {
            for (int i = tid; i < n; i += 512) {
                unsigned int key = skeys[i];
                if ((key & hmask) == pfx) atomicAdd(&hist[(key >> shift) & 255], 1);
            }
        } else {
            for (int i = tid; i < n; i += 512) {
                unsigned int key = gk[i];
                if ((key & hmask) == pfx) atomicAdd(&hist[(key >> shift) & 255], 1);
            }
        }
        __syncthreads();

        if (tid < 32) {                          // warp-scan bin select
            const int lane = tid;
            const int base = lane * 8;
            int c[8]; int s = 0;
            #pragma unroll
            for (int q = 0; q < 8; q++) { c[q] = hist[base + q]; s += c[q]; }
            int excl = s;
            #pragma unroll
            for (int off = 1; off < 32; off <<= 1) {
                int nn = __shfl_up_sync(0xFFFFFFFFu, excl, off);
                if (lane >= off) excl += nn;
            }
            excl -= s;                           // exclusive prefix across lanes
            const int k0 = s_k;
            int bin = 256, cumAt = 0, cum = excl;
            #pragma unroll
            for (int q = 0; q < 8; q++) {
                if (bin == 256 && cum + c[q] > k0) { bin = base + q; cumAt = cum; }
                cum += c[q];
            }
            unsigned int ball = __ballot_sync(0xFFFFFFFFu, bin < 256);
            int src = __ffs(ball) - 1;           // guaranteed: total >= k0+1
            if (lane == src) {
                s_k   = k0 - cumAt;
                s_pfx = pfx | ((unsigned int)bin << shift);
            }
        }
        __syncthreads();
    }

    if (tid == 0) {
        unsigned int key = s_pfx;
        unsigned int u = (key & 0x80000000u) ? (key ^ 0x80000000u) : ~key;
        float med = __uint_as_float(u);
        out[b] = fmaxf(coeffs[0] + coeffs[1] * med, 0.01f);
    }
}

// ---------------- launcher ---------------------------------------------------
extern "C" void kernel_launch(void* const* d_in, const int* in_sizes, int n_in,
                              void* d_out, int out_size) {
    const float* y      = (const float*)d_in[0];
    const float* coeffs = (const float*)d_in[1];
    float*       out    = (float*)d_out;

    init_kernel<<<8, 256>>>();
    stft_kernel<<<NB * NFP, 256>>>(y);
    rt60_kernel<<<NB * NBINS, 128>>>();
    median_kernel<<<NB, 512>>>(coeffs, out);
}